// round 14
// baseline (speedup 1.0000x reference)
#include <cuda_runtime.h>
#include <cuda_bf16.h>
#include <math.h>
#include <stdint.h>

#define BB 4096
#define KK 32
#define DD 1024
#define RR 128

// ---------------- device scratch (allocation-free rule: __device__ globals) ----
__device__ __nv_bfloat16 g_xnt_hi[(size_t)BB * DD];
__device__ __nv_bfloat16 g_xnt_lo[(size_t)BB * DD];
__device__ __nv_bfloat16 g_xnn_hi[(size_t)BB * KK * DD];
__device__ __nv_bfloat16 g_xnn_lo[(size_t)BB * KK * DD];
__device__ __nv_bfloat16 g_ws_hi[(size_t)DD * DD];
__device__ __nv_bfloat16 g_ws_lo[(size_t)DD * DD];
__device__ __nv_bfloat16 g_wn_hi[(size_t)DD * DD];
__device__ __nv_bfloat16 g_wn_lo[(size_t)DD * DD];
__device__ float g_snb[(size_t)BB * KK * DD];
__device__ float g_sself[(size_t)BB * DD];
__device__ float g_ctx[(size_t)BB * DD];

// ---------------- helpers ------------------------------------------------------
__device__ __forceinline__ void cp16(void* smem, const void* gmem) {
    uint32_t s = (uint32_t)__cvta_generic_to_shared(smem);
    asm volatile("cp.async.cg.shared.global [%0], [%1], 16;" :: "r"(s), "l"(gmem));
}
__device__ __forceinline__ void cp_commit() {
    asm volatile("cp.async.commit_group;");
}
template <int N> __device__ __forceinline__ void cp_wait() {
    asm volatile("cp.async.wait_group %0;" :: "n"(N));
}

// bf16 mma m16n8k16, D += A*B (accumulate in place)
__device__ __forceinline__ void mma_bf16(float4& d, const uint32_t a[4], const uint32_t b[2]) {
    asm volatile(
        "mma.sync.aligned.m16n8k16.row.col.f32.bf16.bf16.f32 "
        "{%0,%1,%2,%3}, {%4,%5,%6,%7}, {%8,%9}, {%0,%1,%2,%3};"
        : "+f"(d.x), "+f"(d.y), "+f"(d.z), "+f"(d.w)
        : "r"(a[0]), "r"(a[1]), "r"(a[2]), "r"(a[3]), "r"(b[0]), "r"(b[1]));
}

// ldmatrix x4 (four 8x8 b16 matrices)
__device__ __forceinline__ void ldsm_x4(uint32_t r[4], uint32_t saddr) {
    asm volatile("ldmatrix.sync.aligned.m8n8.x4.shared.b16 {%0,%1,%2,%3}, [%4];"
        : "=r"(r[0]), "=r"(r[1]), "=r"(r[2]), "=r"(r[3]) : "r"(saddr));
}

// FFMA-only exp. Max rel err ~2.4e-6.
__device__ __forceinline__ float fast_exp(float x) {
    float t = x * 1.4426950408889634f;
    int   n = __float2int_rn(t);
    float r = t - (float)n;
    float p = 0.0013333551f;
    p = fmaf(p, r, 0.0096181296f);
    p = fmaf(p, r, 0.05550412f);
    p = fmaf(p, r, 0.2402265f);
    p = fmaf(p, r, 0.69314718f);
    p = fmaf(p, r, 1.0f);
    return __int_as_float(__float_as_int(p) + (n << 23));
}

// ---------------- kernel 0: weight split fp32 -> bf16 hi/lo --------------------
__global__ __launch_bounds__(256)
void wprep_kernel(const float* __restrict__ ws, const float* __restrict__ wn) {
    int i = blockIdx.x * 256 + threadIdx.x;
    float a = __ldg(ws + i);
    __nv_bfloat16 h = __float2bfloat16(a);
    g_ws_hi[i] = h;
    g_ws_lo[i] = __float2bfloat16(a - __bfloat162float(h));
    float b = __ldg(wn + i);
    __nv_bfloat16 h2 = __float2bfloat16(b);
    g_wn_hi[i] = h2;
    g_wn_lo[i] = __float2bfloat16(b - __bfloat162float(h2));
}

// ---------------- kernel 1: LayerNorm -> bf16 hi/lo ----------------------------
__global__ __launch_bounds__(256)
void ln_kernel(const float* __restrict__ tgt, const float* __restrict__ nbr,
               const float* __restrict__ ln_scale, const float* __restrict__ ln_bias)
{
    const int r    = blockIdx.x * 8 + (threadIdx.x >> 5);
    const int lane = threadIdx.x & 31;

    const float* src;
    __nv_bfloat16 *dh, *dl;
    if (r < BB) {
        src = tgt + (size_t)r * DD;
        dh = g_xnt_hi + (size_t)r * DD; dl = g_xnt_lo + (size_t)r * DD;
    } else {
        size_t rn = (size_t)(r - BB);
        src = nbr + rn * DD;
        dh = g_xnn_hi + rn * DD; dl = g_xnn_lo + rn * DD;
    }

    const float4* s4 = (const float4*)src;
    float4 v[8];
    float s = 0.f, q = 0.f;
    #pragma unroll
    for (int j = 0; j < 8; ++j) {
        v[j] = __ldg(s4 + j * 32 + lane);
        s += v[j].x + v[j].y + v[j].z + v[j].w;
        q += v[j].x * v[j].x + v[j].y * v[j].y + v[j].z * v[j].z + v[j].w * v[j].w;
    }
    #pragma unroll
    for (int o = 16; o > 0; o >>= 1) {
        s += __shfl_xor_sync(0xffffffffu, s, o);
        q += __shfl_xor_sync(0xffffffffu, q, o);
    }
    const float mu   = s * (1.0f / 1024.0f);
    const float var  = q * (1.0f / 1024.0f) - mu * mu;
    const float rstd = rsqrtf(var + 1e-5f);

    const float4* sc4 = (const float4*)ln_scale;
    const float4* bi4 = (const float4*)ln_bias;
    #pragma unroll
    for (int j = 0; j < 8; ++j) {
        const float4 sc = __ldg(sc4 + j * 32 + lane);
        const float4 bi = __ldg(bi4 + j * 32 + lane);
        float o0 = (v[j].x - mu) * rstd * sc.x + bi.x;
        float o1 = (v[j].y - mu) * rstd * sc.y + bi.y;
        float o2 = (v[j].z - mu) * rstd * sc.z + bi.z;
        float o3 = (v[j].w - mu) * rstd * sc.w + bi.w;
        __nv_bfloat16 h0 = __float2bfloat16(o0), h1 = __float2bfloat16(o1);
        __nv_bfloat16 h2 = __float2bfloat16(o2), h3 = __float2bfloat16(o3);
        __nv_bfloat16 l0 = __float2bfloat16(o0 - __bfloat162float(h0));
        __nv_bfloat16 l1 = __float2bfloat16(o1 - __bfloat162float(h1));
        __nv_bfloat16 l2 = __float2bfloat16(o2 - __bfloat162float(h2));
        __nv_bfloat16 l3 = __float2bfloat16(o3 - __bfloat162float(h3));
        const int d = (j * 32 + lane) * 4;
        uint2 hv, lv;
        hv.x = (uint32_t)__bfloat16_as_ushort(h0) | ((uint32_t)__bfloat16_as_ushort(h1) << 16);
        hv.y = (uint32_t)__bfloat16_as_ushort(h2) | ((uint32_t)__bfloat16_as_ushort(h3) << 16);
        lv.x = (uint32_t)__bfloat16_as_ushort(l0) | ((uint32_t)__bfloat16_as_ushort(l1) << 16);
        lv.y = (uint32_t)__bfloat16_as_ushort(l2) | ((uint32_t)__bfloat16_as_ushort(l3) << 16);
        *(uint2*)&dh[d] = hv;
        *(uint2*)&dl[d] = lv;
    }
}

// ---------------- kernel 2: merged 3xBF16 HMMA GEMM (ldmatrix, 2 CTA/SM) -------
// Row-space concat: y-tiles [0,1024) = neighbor rows, [1024,1056) = target rows.
// CTA tile 128x128, K-slab 32 bf16, double-buffered cp.async.
// 256 thr = 8 warps (4m x 2n), warp tile 32x64. Fragments via ldmatrix.x4
// (mapping bit-validated in R9). 3 terms: acc += Ah*Bh + Ah*Bl + Al*Bh.
#define ROWB 80                                 // 32 bf16 (64B) + 16B pad
#define ARR_B (128 * ROWB)                      // 10240 bytes per array
#define STAGE_B (4 * ARR_B)                     // 40960 per stage
#define GEMM_SMEM (2 * STAGE_B)                 // 81920 -> 2 CTAs/SM

__global__ __launch_bounds__(256, 2)
void gemm_all_kernel()
{
    extern __shared__ char smem[];

    const int ty = blockIdx.y;
    const __nv_bfloat16 *Ah, *Al, *Bh, *Bl;
    float* C;
    int m0;
    if (ty < (BB * KK) / 128) {
        Ah = g_xnn_hi; Al = g_xnn_lo; Bh = g_wn_hi; Bl = g_wn_lo;
        C = g_snb; m0 = ty * 128;
    } else {
        Ah = g_xnt_hi; Al = g_xnt_lo; Bh = g_ws_hi; Bl = g_ws_lo;
        C = g_sself; m0 = (ty - (BB * KK) / 128) * 128;
    }

    const int t    = threadIdx.x;
    const int e0   = blockIdx.x * 128;
    const int warp = t >> 5, lane = t & 31;
    const int g    = lane >> 2, tig = lane & 3;
    const int wm   = warp >> 1, wnb = warp & 1;
    const int mbase = wm * 32, nbase = wnb * 64;

    const uint32_t smem_s = (uint32_t)__cvta_generic_to_shared(smem);

    // ldmatrix lane offsets (R9-validated on this exact 80B-row layout):
    // A x4: lanes 0-15 -> rows m+0..15, lanes 16-31 -> same rows @k8 (+16B)
    const uint32_t a_off = (uint32_t)(mbase + (lane & 15)) * ROWB + ((lane & 16) ? 16u : 0u);
    // B x4: lanes 0-7 (n0-7,k0), 8-15 (n0-7,k8), 16-23 (n8-15,k0), 24-31 (n8-15,k8)
    const uint32_t b_off = (uint32_t)(nbase + (lane & 7) + ((lane & 16) ? 8u : 0u)) * ROWB
                         + ((lane & 8) ? 16u : 0u);

    float4 acc[2][8];
    #pragma unroll
    for (int i = 0; i < 2; ++i)
        #pragma unroll
        for (int j = 0; j < 8; ++j) acc[i][j] = make_float4(0.f, 0.f, 0.f, 0.f);

    // stage slab (32 k) into buffer: 4 arrays x 512 16B-chunks = 8 cp16/thread
    #define STAGE(slab, buf)                                                     \
        do {                                                                     \
            const int k0 = (slab) * 32;                                          \
            char* bufp = smem + (buf) * STAGE_B;                                 \
            _Pragma("unroll")                                                    \
            for (int j = 0; j < 8; ++j) {                                        \
                int i   = t + 256 * j;                                           \
                int arr = i >> 9;                                                \
                int idx = i & 511;                                               \
                int row = idx >> 2, c = idx & 3;                                 \
                const __nv_bfloat16* src =                                       \
                    (arr == 0 ? Ah : arr == 1 ? Al : arr == 2 ? Bh : Bl)         \
                    + (size_t)((arr < 2 ? m0 : e0) + row) * DD + k0 + c * 8;     \
                cp16(bufp + arr * ARR_B + row * ROWB + c * 16, src);             \
            }                                                                    \
            cp_commit();                                                         \
        } while (0)

    STAGE(0, 0);
    STAGE(1, 1);

    for (int kt = 0; kt < 32; ++kt) {
        if (kt + 1 < 32) cp_wait<1>(); else cp_wait<0>();
        __syncthreads();
        const uint32_t sbuf = smem_s + (uint32_t)(kt & 1) * STAGE_B;

        #pragma unroll
        for (int s2 = 0; s2 < 2; ++s2) {        // two k16 steps per slab
            const uint32_t kb = (uint32_t)s2 * 32;
            uint32_t ah[2][4], al[2][4];
            #pragma unroll
            for (int mt = 0; mt < 2; ++mt) {
                const uint32_t ab = a_off + (uint32_t)mt * (16 * ROWB) + kb;
                ldsm_x4(ah[mt], sbuf + ab);
                ldsm_x4(al[mt], sbuf + ARR_B + ab);
            }
            // 4 np groups of 16 e-cols; B frags ldmatrix'd per group (8+8 regs live)
            #pragma unroll
            for (int np = 0; np < 4; ++np) {
                const uint32_t bb = b_off + (uint32_t)np * (16 * ROWB) + kb;
                uint32_t bh[4], bl[4];
                ldsm_x4(bh, sbuf + 2 * ARR_B + bb);
                ldsm_x4(bl, sbuf + 3 * ARR_B + bb);
                #pragma unroll
                for (int sub = 0; sub < 2; ++sub) {
                    const int nt = np * 2 + sub;
                    uint32_t bhf[2] = { bh[sub * 2], bh[sub * 2 + 1] };
                    uint32_t blf[2] = { bl[sub * 2], bl[sub * 2 + 1] };
                    mma_bf16(acc[0][nt], ah[0], bhf);
                    mma_bf16(acc[0][nt], ah[0], blf);
                    mma_bf16(acc[0][nt], al[0], bhf);
                    mma_bf16(acc[1][nt], ah[1], bhf);
                    mma_bf16(acc[1][nt], ah[1], blf);
                    mma_bf16(acc[1][nt], al[1], bhf);
                }
            }
        }
        __syncthreads();
        if (kt + 2 < 32) STAGE(kt + 2, kt & 1);
    }
    #undef STAGE

    #pragma unroll
    for (int mt = 0; mt < 2; ++mt) {
        const int r0 = m0 + mbase + mt * 16 + g;
        #pragma unroll
        for (int nt = 0; nt < 8; ++nt) {
            const int e = e0 + nbase + nt * 8 + 2 * tig;
            const float4 v = acc[mt][nt];
            *(float2*)&C[(size_t)r0 * DD + e]       = make_float2(v.x, v.y);
            *(float2*)&C[(size_t)(r0 + 8) * DD + e] = make_float2(v.z, v.w);
        }
    }
}

// ---------------- kernel 3: epilogue -------------------------------------------
__global__ __launch_bounds__(256)
void epilogue_kernel(const float* __restrict__ dist, const float* __restrict__ beta_p,
                     const float* __restrict__ b_self, const float* __restrict__ b_nb,
                     float* __restrict__ out_selfw, float* __restrict__ out_nbw)
{
    __shared__ float dw[32];
    const int bx = blockIdx.x;
    const int b  = bx >> 2;
    const int e  = ((bx & 3) << 8) + threadIdx.x;

    if (threadIdx.x < 32) {
        float dv = __ldg(dist + (size_t)b * KK + threadIdx.x);
        dw[threadIdx.x] = expf(dv * (-2.0f / (100.0f + 1e-8f)));
    }
    __syncthreads();

    float acc[33];
    acc[0] = g_sself[(size_t)b * DD + e] + __ldg(b_self + e);
    const float bn = __ldg(b_nb + e);
    #pragma unroll
    for (int k = 0; k < KK; ++k)
        acc[k + 1] = (g_snb[((size_t)b * KK + k) * DD + e] + bn) * dw[k];

    float mx = acc[0];
    #pragma unroll
    for (int m = 1; m < 33; ++m) mx = fmaxf(mx, acc[m]);
    float sum = 0.f;
    #pragma unroll
    for (int m = 0; m < 33; ++m) { acc[m] = fast_exp(acc[m] - mx); sum += acc[m]; }
    const float inv = 1.0f / sum;
    #pragma unroll
    for (int m = 0; m < 33; ++m) {
        const float w = acc[m] * inv;
        acc[m] = (fabsf(w) >= 0.01f) ? w : 0.0f;
    }

    const float beta = __ldg(beta_p);
    out_selfw[(size_t)b * DD + e] = acc[0];
    const size_t ti = (size_t)b * DD + e;
    const float xnt = __bfloat162float(g_xnt_hi[ti]) + __bfloat162float(g_xnt_lo[ti]);
    float ctx = beta * acc[0] * xnt;
    float ns  = 0.f;
    #pragma unroll
    for (int k = 0; k < KK; ++k) {
        const float w = acc[k + 1];
        const size_t ni = ((size_t)b * KK + k) * DD + e;
        out_nbw[ni] = w;
        const float xnn = __bfloat162float(g_xnn_hi[ni]) + __bfloat162float(g_xnn_lo[ni]);
        ns += w * xnn;
    }
    ctx += (1.0f - beta) * ns;
    g_ctx[(size_t)b * DD + e] = ctx;
}

// ---------------- kernel 4: reduced = leaky_relu(ctx @ w_red^T + b_red) --------
__global__ __launch_bounds__(256)
void reduce_kernel(const float* __restrict__ w_red, const float* __restrict__ b_red,
                   float* __restrict__ out_red)
{
    __shared__ float ctx_s[32 * 33];
    __shared__ float w_s[128 * 33];

    const int t  = threadIdx.x;
    const int b0 = blockIdx.x * 32;
    const int tb = t >> 4;
    const int tr = t & 15;

    float acc[2][8];
    #pragma unroll
    for (int i = 0; i < 8; ++i) { acc[0][i] = 0.f; acc[1][i] = 0.f; }

    for (int d0 = 0; d0 < DD; d0 += 32) {
        __syncthreads();
        #pragma unroll
        for (int j = 0; j < 4; ++j) {
            int i = t + 256 * j;
            int row = i >> 5, col = i & 31;
            ctx_s[row * 33 + col] = g_ctx[(size_t)(b0 + row) * DD + d0 + col];
        }
        #pragma unroll
        for (int j = 0; j < 16; ++j) {
            int i = t + 256 * j;
            int row = i >> 5, col = i & 31;
            w_s[row * 33 + col] = __ldg(w_red + (size_t)row * DD + d0 + col);
        }
        __syncthreads();

        #pragma unroll
        for (int dl = 0; dl < 32; ++dl) {
            float c0 = ctx_s[tb * 33 + dl];
            float c1 = ctx_s[(tb + 16) * 33 + dl];
            #pragma unroll
            for (int i = 0; i < 8; ++i) {
                float wv = w_s[(tr + 16 * i) * 33 + dl];
                acc[0][i] += c0 * wv;
                acc[1][i] += c1 * wv;
            }
        }
    }

    #pragma unroll
    for (int i = 0; i < 8; ++i) {
        int r = tr + 16 * i;
        float bias = __ldg(b_red + r);
        float v0 = acc[0][i] + bias;
        float v1 = acc[1][i] + bias;
        v0 = v0 > 0.f ? v0 : 0.01f * v0;
        v1 = v1 > 0.f ? v1 : 0.01f * v1;
        out_red[(size_t)(b0 + tb) * RR + r]      = v0;
        out_red[(size_t)(b0 + tb + 16) * RR + r] = v1;
    }
}

// ---------------------------------------------------------------------------
extern "C" void kernel_launch(void* const* d_in, const int* in_sizes, int n_in,
                              void* d_out, int out_size)
{
    (void)in_sizes; (void)n_in; (void)out_size;

    const float* tgt      = (const float*)d_in[0];
    const float* nbr      = (const float*)d_in[1];
    const float* dist     = (const float*)d_in[2];
    const float* beta_p   = (const float*)d_in[3];
    const float* ln_scale = (const float*)d_in[4];
    const float* ln_bias  = (const float*)d_in[5];
    const float* w_self   = (const float*)d_in[6];
    const float* b_self   = (const float*)d_in[7];
    const float* w_nb     = (const float*)d_in[8];
    const float* b_nb     = (const float*)d_in[9];
    const float* w_red    = (const float*)d_in[10];
    const float* b_red    = (const float*)d_in[11];

    float* out       = (float*)d_out;
    float* out_red   = out;                              // B*R
    float* out_selfw = out + (size_t)BB * RR;            // B*D
    float* out_nbw   = out_selfw + (size_t)BB * DD;      // B*K*D

    cudaFuncSetAttribute(gemm_all_kernel,
                         cudaFuncAttributeMaxDynamicSharedMemorySize, GEMM_SMEM);

    wprep_kernel<<<DD * DD / 256, 256>>>(w_self, w_nb);
    ln_kernel<<<(BB * 33) / 8, 256>>>(tgt, nbr, ln_scale, ln_bias);

    // merged: y in [0,1024) -> neighbor GEMM, [1024,1056) -> self GEMM
    gemm_all_kernel<<<dim3(DD / 128, (BB * KK) / 128 + BB / 128), 256, GEMM_SMEM>>>();

    epilogue_kernel<<<BB * 4, 256>>>(dist, beta_p, b_self, b_nb, out_selfw, out_nbw);
    reduce_kernel<<<BB / 32, 256>>>(w_red, b_red, out_red);
}

// round 15
// speedup vs baseline: 1.0005x; 1.0005x over previous
#include <cuda_runtime.h>
#include <cuda_bf16.h>
#include <math.h>
#include <stdint.h>

#define BB 4096
#define KK 32
#define DD 1024
#define RR 128

// ---------------- device scratch (allocation-free rule: __device__ globals) ----
__device__ __nv_bfloat16 g_xnt_hi[(size_t)BB * DD];
__device__ __nv_bfloat16 g_xnt_lo[(size_t)BB * DD];
__device__ __nv_bfloat16 g_xnn_hi[(size_t)BB * KK * DD];
__device__ __nv_bfloat16 g_xnn_lo[(size_t)BB * KK * DD];
__device__ __nv_bfloat16 g_ws_hi[(size_t)DD * DD];
__device__ __nv_bfloat16 g_ws_lo[(size_t)DD * DD];
__device__ __nv_bfloat16 g_wn_hi[(size_t)DD * DD];
__device__ __nv_bfloat16 g_wn_lo[(size_t)DD * DD];
__device__ float g_snb[(size_t)BB * KK * DD];
__device__ float g_sself[(size_t)BB * DD];
__device__ float g_ctx[(size_t)BB * DD];

// ---------------- helpers ------------------------------------------------------
__device__ __forceinline__ void cp16(void* smem, const void* gmem) {
    uint32_t s = (uint32_t)__cvta_generic_to_shared(smem);
    asm volatile("cp.async.cg.shared.global [%0], [%1], 16;" :: "r"(s), "l"(gmem));
}
__device__ __forceinline__ void cp_commit() {
    asm volatile("cp.async.commit_group;");
}
template <int N> __device__ __forceinline__ void cp_wait() {
    asm volatile("cp.async.wait_group %0;" :: "n"(N));
}

// bf16 mma m16n8k16, D += A*B (accumulate in place)
__device__ __forceinline__ void mma_bf16(float4& d, const uint32_t a[4], const uint32_t b[2]) {
    asm volatile(
        "mma.sync.aligned.m16n8k16.row.col.f32.bf16.bf16.f32 "
        "{%0,%1,%2,%3}, {%4,%5,%6,%7}, {%8,%9}, {%0,%1,%2,%3};"
        : "+f"(d.x), "+f"(d.y), "+f"(d.z), "+f"(d.w)
        : "r"(a[0]), "r"(a[1]), "r"(a[2]), "r"(a[3]), "r"(b[0]), "r"(b[1]));
}

// ldmatrix x4 (four 8x8 b16 matrices)
__device__ __forceinline__ void ldsm_x4(uint32_t r[4], uint32_t saddr) {
    asm volatile("ldmatrix.sync.aligned.m8n8.x4.shared.b16 {%0,%1,%2,%3}, [%4];"
        : "=r"(r[0]), "=r"(r[1]), "=r"(r[2]), "=r"(r[3]) : "r"(saddr));
}

// FFMA-only exp. Max rel err ~2.4e-6.
__device__ __forceinline__ float fast_exp(float x) {
    float t = x * 1.4426950408889634f;
    int   n = __float2int_rn(t);
    float r = t - (float)n;
    float p = 0.0013333551f;
    p = fmaf(p, r, 0.0096181296f);
    p = fmaf(p, r, 0.05550412f);
    p = fmaf(p, r, 0.2402265f);
    p = fmaf(p, r, 0.69314718f);
    p = fmaf(p, r, 1.0f);
    return __int_as_float(__float_as_int(p) + (n << 23));
}

// ---------------- kernel 0: weight split fp32 -> bf16 hi/lo --------------------
__global__ __launch_bounds__(256)
void wprep_kernel(const float* __restrict__ ws, const float* __restrict__ wn) {
    int i = blockIdx.x * 256 + threadIdx.x;
    float a = __ldg(ws + i);
    __nv_bfloat16 h = __float2bfloat16(a);
    g_ws_hi[i] = h;
    g_ws_lo[i] = __float2bfloat16(a - __bfloat162float(h));
    float b = __ldg(wn + i);
    __nv_bfloat16 h2 = __float2bfloat16(b);
    g_wn_hi[i] = h2;
    g_wn_lo[i] = __float2bfloat16(b - __bfloat162float(h2));
}

// ---------------- kernel 1: LayerNorm -> bf16 hi/lo ----------------------------
__global__ __launch_bounds__(256)
void ln_kernel(const float* __restrict__ tgt, const float* __restrict__ nbr,
               const float* __restrict__ ln_scale, const float* __restrict__ ln_bias)
{
    const int r    = blockIdx.x * 8 + (threadIdx.x >> 5);
    const int lane = threadIdx.x & 31;

    const float* src;
    __nv_bfloat16 *dh, *dl;
    if (r < BB) {
        src = tgt + (size_t)r * DD;
        dh = g_xnt_hi + (size_t)r * DD; dl = g_xnt_lo + (size_t)r * DD;
    } else {
        size_t rn = (size_t)(r - BB);
        src = nbr + rn * DD;
        dh = g_xnn_hi + rn * DD; dl = g_xnn_lo + rn * DD;
    }

    const float4* s4 = (const float4*)src;
    float4 v[8];
    float s = 0.f, q = 0.f;
    #pragma unroll
    for (int j = 0; j < 8; ++j) {
        v[j] = __ldg(s4 + j * 32 + lane);
        s += v[j].x + v[j].y + v[j].z + v[j].w;
        q += v[j].x * v[j].x + v[j].y * v[j].y + v[j].z * v[j].z + v[j].w * v[j].w;
    }
    #pragma unroll
    for (int o = 16; o > 0; o >>= 1) {
        s += __shfl_xor_sync(0xffffffffu, s, o);
        q += __shfl_xor_sync(0xffffffffu, q, o);
    }
    const float mu   = s * (1.0f / 1024.0f);
    const float var  = q * (1.0f / 1024.0f) - mu * mu;
    const float rstd = rsqrtf(var + 1e-5f);

    const float4* sc4 = (const float4*)ln_scale;
    const float4* bi4 = (const float4*)ln_bias;
    #pragma unroll
    for (int j = 0; j < 8; ++j) {
        const float4 sc = __ldg(sc4 + j * 32 + lane);
        const float4 bi = __ldg(bi4 + j * 32 + lane);
        float o0 = (v[j].x - mu) * rstd * sc.x + bi.x;
        float o1 = (v[j].y - mu) * rstd * sc.y + bi.y;
        float o2 = (v[j].z - mu) * rstd * sc.z + bi.z;
        float o3 = (v[j].w - mu) * rstd * sc.w + bi.w;
        __nv_bfloat16 h0 = __float2bfloat16(o0), h1 = __float2bfloat16(o1);
        __nv_bfloat16 h2 = __float2bfloat16(o2), h3 = __float2bfloat16(o3);
        __nv_bfloat16 l0 = __float2bfloat16(o0 - __bfloat162float(h0));
        __nv_bfloat16 l1 = __float2bfloat16(o1 - __bfloat162float(h1));
        __nv_bfloat16 l2 = __float2bfloat16(o2 - __bfloat162float(h2));
        __nv_bfloat16 l3 = __float2bfloat16(o3 - __bfloat162float(h3));
        const int d = (j * 32 + lane) * 4;
        uint2 hv, lv;
        hv.x = (uint32_t)__bfloat16_as_ushort(h0) | ((uint32_t)__bfloat16_as_ushort(h1) << 16);
        hv.y = (uint32_t)__bfloat16_as_ushort(h2) | ((uint32_t)__bfloat16_as_ushort(h3) << 16);
        lv.x = (uint32_t)__bfloat16_as_ushort(l0) | ((uint32_t)__bfloat16_as_ushort(l1) << 16);
        lv.y = (uint32_t)__bfloat16_as_ushort(l2) | ((uint32_t)__bfloat16_as_ushort(l3) << 16);
        *(uint2*)&dh[d] = hv;
        *(uint2*)&dl[d] = lv;
    }
}

// ---------------- kernel 2: merged 3xBF16 HMMA GEMM (ldmatrix, 2 CTA/SM) -------
// Row-space concat: y-tiles [0,1024) = neighbor rows, [1024,1056) = target rows.
// CTA tile 128x128, K-slab 32 bf16, double-buffered cp.async.
// 256 thr = 8 warps (4m x 2n), warp tile 32x64. Fragments via ldmatrix.x4
// (mapping bit-validated in R9). 3 terms: acc += Ah*Bh + Ah*Bl + Al*Bh.
#define ROWB 80                                 // 32 bf16 (64B) + 16B pad
#define ARR_B (128 * ROWB)                      // 10240 bytes per array
#define STAGE_B (4 * ARR_B)                     // 40960 per stage
#define GEMM_SMEM (2 * STAGE_B)                 // 81920 -> 2 CTAs/SM

__global__ __launch_bounds__(256, 2)
void gemm_all_kernel()
{
    extern __shared__ char smem[];

    const int ty = blockIdx.y;
    const __nv_bfloat16 *Ah, *Al, *Bh, *Bl;
    float* C;
    int m0;
    if (ty < (BB * KK) / 128) {
        Ah = g_xnn_hi; Al = g_xnn_lo; Bh = g_wn_hi; Bl = g_wn_lo;
        C = g_snb; m0 = ty * 128;
    } else {
        Ah = g_xnt_hi; Al = g_xnt_lo; Bh = g_ws_hi; Bl = g_ws_lo;
        C = g_sself; m0 = (ty - (BB * KK) / 128) * 128;
    }

    const int t    = threadIdx.x;
    const int e0   = blockIdx.x * 128;
    const int warp = t >> 5, lane = t & 31;
    const int g    = lane >> 2, tig = lane & 3;
    const int wm   = warp >> 1, wnb = warp & 1;
    const int mbase = wm * 32, nbase = wnb * 64;

    const uint32_t smem_s = (uint32_t)__cvta_generic_to_shared(smem);

    // ldmatrix lane offsets (R9-validated on this exact 80B-row layout):
    // A x4: lanes 0-15 -> rows m+0..15, lanes 16-31 -> same rows @k8 (+16B)
    const uint32_t a_off = (uint32_t)(mbase + (lane & 15)) * ROWB + ((lane & 16) ? 16u : 0u);
    // B x4: lanes 0-7 (n0-7,k0), 8-15 (n0-7,k8), 16-23 (n8-15,k0), 24-31 (n8-15,k8)
    const uint32_t b_off = (uint32_t)(nbase + (lane & 7) + ((lane & 16) ? 8u : 0u)) * ROWB
                         + ((lane & 8) ? 16u : 0u);

    float4 acc[2][8];
    #pragma unroll
    for (int i = 0; i < 2; ++i)
        #pragma unroll
        for (int j = 0; j < 8; ++j) acc[i][j] = make_float4(0.f, 0.f, 0.f, 0.f);

    // stage slab (32 k) into buffer: 4 arrays x 512 16B-chunks = 8 cp16/thread
    #define STAGE(slab, buf)                                                     \
        do {                                                                     \
            const int k0 = (slab) * 32;                                          \
            char* bufp = smem + (buf) * STAGE_B;                                 \
            _Pragma("unroll")                                                    \
            for (int j = 0; j < 8; ++j) {                                        \
                int i   = t + 256 * j;                                           \
                int arr = i >> 9;                                                \
                int idx = i & 511;                                               \
                int row = idx >> 2, c = idx & 3;                                 \
                const __nv_bfloat16* src =                                       \
                    (arr == 0 ? Ah : arr == 1 ? Al : arr == 2 ? Bh : Bl)         \
                    + (size_t)((arr < 2 ? m0 : e0) + row) * DD + k0 + c * 8;     \
                cp16(bufp + arr * ARR_B + row * ROWB + c * 16, src);             \
            }                                                                    \
            cp_commit();                                                         \
        } while (0)

    STAGE(0, 0);
    STAGE(1, 1);

    for (int kt = 0; kt < 32; ++kt) {
        if (kt + 1 < 32) cp_wait<1>(); else cp_wait<0>();
        __syncthreads();
        const uint32_t sbuf = smem_s + (uint32_t)(kt & 1) * STAGE_B;

        #pragma unroll
        for (int s2 = 0; s2 < 2; ++s2) {        // two k16 steps per slab
            const uint32_t kb = (uint32_t)s2 * 32;
            uint32_t ah[2][4], al[2][4];
            #pragma unroll
            for (int mt = 0; mt < 2; ++mt) {
                const uint32_t ab = a_off + (uint32_t)mt * (16 * ROWB) + kb;
                ldsm_x4(ah[mt], sbuf + ab);
                ldsm_x4(al[mt], sbuf + ARR_B + ab);
            }
            // 4 np groups of 16 e-cols; B frags ldmatrix'd per group (8+8 regs live)
            #pragma unroll
            for (int np = 0; np < 4; ++np) {
                const uint32_t bb = b_off + (uint32_t)np * (16 * ROWB) + kb;
                uint32_t bh[4], bl[4];
                ldsm_x4(bh, sbuf + 2 * ARR_B + bb);
                ldsm_x4(bl, sbuf + 3 * ARR_B + bb);
                #pragma unroll
                for (int sub = 0; sub < 2; ++sub) {
                    const int nt = np * 2 + sub;
                    uint32_t bhf[2] = { bh[sub * 2], bh[sub * 2 + 1] };
                    uint32_t blf[2] = { bl[sub * 2], bl[sub * 2 + 1] };
                    mma_bf16(acc[0][nt], ah[0], bhf);
                    mma_bf16(acc[0][nt], ah[0], blf);
                    mma_bf16(acc[0][nt], al[0], bhf);
                    mma_bf16(acc[1][nt], ah[1], bhf);
                    mma_bf16(acc[1][nt], ah[1], blf);
                    mma_bf16(acc[1][nt], al[1], bhf);
                }
            }
        }
        __syncthreads();
        if (kt + 2 < 32) STAGE(kt + 2, kt & 1);
    }
    #undef STAGE

    #pragma unroll
    for (int mt = 0; mt < 2; ++mt) {
        const int r0 = m0 + mbase + mt * 16 + g;
        #pragma unroll
        for (int nt = 0; nt < 8; ++nt) {
            const int e = e0 + nbase + nt * 8 + 2 * tig;
            const float4 v = acc[mt][nt];
            *(float2*)&C[(size_t)r0 * DD + e]       = make_float2(v.x, v.y);
            *(float2*)&C[(size_t)(r0 + 8) * DD + e] = make_float2(v.z, v.w);
        }
    }
}

// ---------------- kernel 3: epilogue -------------------------------------------
__global__ __launch_bounds__(256)
void epilogue_kernel(const float* __restrict__ dist, const float* __restrict__ beta_p,
                     const float* __restrict__ b_self, const float* __restrict__ b_nb,
                     float* __restrict__ out_selfw, float* __restrict__ out_nbw)
{
    __shared__ float dw[32];
    const int bx = blockIdx.x;
    const int b  = bx >> 2;
    const int e  = ((bx & 3) << 8) + threadIdx.x;

    if (threadIdx.x < 32) {
        float dv = __ldg(dist + (size_t)b * KK + threadIdx.x);
        dw[threadIdx.x] = expf(dv * (-2.0f / (100.0f + 1e-8f)));
    }
    __syncthreads();

    float acc[33];
    acc[0] = g_sself[(size_t)b * DD + e] + __ldg(b_self + e);
    const float bn = __ldg(b_nb + e);
    #pragma unroll
    for (int k = 0; k < KK; ++k)
        acc[k + 1] = (g_snb[((size_t)b * KK + k) * DD + e] + bn) * dw[k];

    float mx = acc[0];
    #pragma unroll
    for (int m = 1; m < 33; ++m) mx = fmaxf(mx, acc[m]);
    float sum = 0.f;
    #pragma unroll
    for (int m = 0; m < 33; ++m) { acc[m] = fast_exp(acc[m] - mx); sum += acc[m]; }
    const float inv = 1.0f / sum;
    #pragma unroll
    for (int m = 0; m < 33; ++m) {
        const float w = acc[m] * inv;
        acc[m] = (fabsf(w) >= 0.01f) ? w : 0.0f;
    }

    const float beta = __ldg(beta_p);
    out_selfw[(size_t)b * DD + e] = acc[0];
    const size_t ti = (size_t)b * DD + e;
    const float xnt = __bfloat162float(g_xnt_hi[ti]) + __bfloat162float(g_xnt_lo[ti]);
    float ctx = beta * acc[0] * xnt;
    float ns  = 0.f;
    #pragma unroll
    for (int k = 0; k < KK; ++k) {
        const float w = acc[k + 1];
        const size_t ni = ((size_t)b * KK + k) * DD + e;
        out_nbw[ni] = w;
        const float xnn = __bfloat162float(g_xnn_hi[ni]) + __bfloat162float(g_xnn_lo[ni]);
        ns += w * xnn;
    }
    ctx += (1.0f - beta) * ns;
    g_ctx[(size_t)b * DD + e] = ctx;
}

// ---------------- kernel 4: reduced = leaky_relu(ctx @ w_red^T + b_red) --------
__global__ __launch_bounds__(256)
void reduce_kernel(const float* __restrict__ w_red, const float* __restrict__ b_red,
                   float* __restrict__ out_red)
{
    __shared__ float ctx_s[32 * 33];
    __shared__ float w_s[128 * 33];

    const int t  = threadIdx.x;
    const int b0 = blockIdx.x * 32;
    const int tb = t >> 4;
    const int tr = t & 15;

    float acc[2][8];
    #pragma unroll
    for (int i = 0; i < 8; ++i) { acc[0][i] = 0.f; acc[1][i] = 0.f; }

    for (int d0 = 0; d0 < DD; d0 += 32) {
        __syncthreads();
        #pragma unroll
        for (int j = 0; j < 4; ++j) {
            int i = t + 256 * j;
            int row = i >> 5, col = i & 31;
            ctx_s[row * 33 + col] = g_ctx[(size_t)(b0 + row) * DD + d0 + col];
        }
        #pragma unroll
        for (int j = 0; j < 16; ++j) {
            int i = t + 256 * j;
            int row = i >> 5, col = i & 31;
            w_s[row * 33 + col] = __ldg(w_red + (size_t)row * DD + d0 + col);
        }
        __syncthreads();

        #pragma unroll
        for (int dl = 0; dl < 32; ++dl) {
            float c0 = ctx_s[tb * 33 + dl];
            float c1 = ctx_s[(tb + 16) * 33 + dl];
            #pragma unroll
            for (int i = 0; i < 8; ++i) {
                float wv = w_s[(tr + 16 * i) * 33 + dl];
                acc[0][i] += c0 * wv;
                acc[1][i] += c1 * wv;
            }
        }
    }

    #pragma unroll
    for (int i = 0; i < 8; ++i) {
        int r = tr + 16 * i;
        float bias = __ldg(b_red + r);
        float v0 = acc[0][i] + bias;
        float v1 = acc[1][i] + bias;
        v0 = v0 > 0.f ? v0 : 0.01f * v0;
        v1 = v1 > 0.f ? v1 : 0.01f * v1;
        out_red[(size_t)(b0 + tb) * RR + r]      = v0;
        out_red[(size_t)(b0 + tb + 16) * RR + r] = v1;
    }
}

// ---------------------------------------------------------------------------
extern "C" void kernel_launch(void* const* d_in, const int* in_sizes, int n_in,
                              void* d_out, int out_size)
{
    (void)in_sizes; (void)n_in; (void)out_size;

    const float* tgt      = (const float*)d_in[0];
    const float* nbr      = (const float*)d_in[1];
    const float* dist     = (const float*)d_in[2];
    const float* beta_p   = (const float*)d_in[3];
    const float* ln_scale = (const float*)d_in[4];
    const float* ln_bias  = (const float*)d_in[5];
    const float* w_self   = (const float*)d_in[6];
    const float* b_self   = (const float*)d_in[7];
    const float* w_nb     = (const float*)d_in[8];
    const float* b_nb     = (const float*)d_in[9];
    const float* w_red    = (const float*)d_in[10];
    const float* b_red    = (const float*)d_in[11];

    float* out       = (float*)d_out;
    float* out_red   = out;                              // B*R
    float* out_selfw = out + (size_t)BB * RR;            // B*D
    float* out_nbw   = out_selfw + (size_t)BB * DD;      // B*K*D

    cudaFuncSetAttribute(gemm_all_kernel,
                         cudaFuncAttributeMaxDynamicSharedMemorySize, GEMM_SMEM);

    wprep_kernel<<<DD * DD / 256, 256>>>(w_self, w_nb);
    ln_kernel<<<(BB * 33) / 8, 256>>>(tgt, nbr, ln_scale, ln_bias);

    // merged: y in [0,1024) -> neighbor GEMM, [1024,1056) -> self GEMM
    gemm_all_kernel<<<dim3(DD / 128, (BB * KK) / 128 + BB / 128), 256, GEMM_SMEM>>>();

    epilogue_kernel<<<BB * 4, 256>>>(dist, beta_p, b_self, b_nb, out_selfw, out_nbw);
    reduce_kernel<<<BB / 32, 256>>>(w_red, b_red, out_red);
}

// round 16
// speedup vs baseline: 1.0009x; 1.0004x over previous
#include <cuda_runtime.h>
#include <cuda_bf16.h>
#include <math.h>
#include <stdint.h>

#define BB 4096
#define KK 32
#define DD 1024
#define RR 128

// ---------------- device scratch (allocation-free rule: __device__ globals) ----
__device__ __nv_bfloat16 g_xnt_hi[(size_t)BB * DD];
__device__ __nv_bfloat16 g_xnt_lo[(size_t)BB * DD];
__device__ __nv_bfloat16 g_xnn_hi[(size_t)BB * KK * DD];
__device__ __nv_bfloat16 g_xnn_lo[(size_t)BB * KK * DD];
__device__ __nv_bfloat16 g_ws_hi[(size_t)DD * DD];
__device__ __nv_bfloat16 g_ws_lo[(size_t)DD * DD];
__device__ __nv_bfloat16 g_wn_hi[(size_t)DD * DD];
__device__ __nv_bfloat16 g_wn_lo[(size_t)DD * DD];
__device__ float g_snb[(size_t)BB * KK * DD];
__device__ float g_sself[(size_t)BB * DD];
__device__ float g_ctx[(size_t)BB * DD];

// ---------------- helpers ------------------------------------------------------
__device__ __forceinline__ void cp16(void* smem, const void* gmem) {
    uint32_t s = (uint32_t)__cvta_generic_to_shared(smem);
    asm volatile("cp.async.cg.shared.global [%0], [%1], 16;" :: "r"(s), "l"(gmem));
}
__device__ __forceinline__ void cp_commit() {
    asm volatile("cp.async.commit_group;");
}
template <int N> __device__ __forceinline__ void cp_wait() {
    asm volatile("cp.async.wait_group %0;" :: "n"(N));
}

// bf16 mma m16n8k16, D += A*B (accumulate in place)
__device__ __forceinline__ void mma_bf16(float4& d, const uint32_t a[4], const uint32_t b[2]) {
    asm volatile(
        "mma.sync.aligned.m16n8k16.row.col.f32.bf16.bf16.f32 "
        "{%0,%1,%2,%3}, {%4,%5,%6,%7}, {%8,%9}, {%0,%1,%2,%3};"
        : "+f"(d.x), "+f"(d.y), "+f"(d.z), "+f"(d.w)
        : "r"(a[0]), "r"(a[1]), "r"(a[2]), "r"(a[3]), "r"(b[0]), "r"(b[1]));
}

// ldmatrix x4 (four 8x8 b16 matrices)
__device__ __forceinline__ void ldsm_x4(uint32_t r[4], uint32_t saddr) {
    asm volatile("ldmatrix.sync.aligned.m8n8.x4.shared.b16 {%0,%1,%2,%3}, [%4];"
        : "=r"(r[0]), "=r"(r[1]), "=r"(r[2]), "=r"(r[3]) : "r"(saddr));
}

// FFMA-only exp. Max rel err ~2.4e-6.
__device__ __forceinline__ float fast_exp(float x) {
    float t = x * 1.4426950408889634f;
    int   n = __float2int_rn(t);
    float r = t - (float)n;
    float p = 0.0013333551f;
    p = fmaf(p, r, 0.0096181296f);
    p = fmaf(p, r, 0.05550412f);
    p = fmaf(p, r, 0.2402265f);
    p = fmaf(p, r, 0.69314718f);
    p = fmaf(p, r, 1.0f);
    return __int_as_float(__float_as_int(p) + (n << 23));
}

// ---------------- kernel 0: weight split fp32 -> bf16 hi/lo --------------------
__global__ __launch_bounds__(256)
void wprep_kernel(const float* __restrict__ ws, const float* __restrict__ wn) {
    int i = blockIdx.x * 256 + threadIdx.x;
    float a = __ldg(ws + i);
    __nv_bfloat16 h = __float2bfloat16(a);
    g_ws_hi[i] = h;
    g_ws_lo[i] = __float2bfloat16(a - __bfloat162float(h));
    float b = __ldg(wn + i);
    __nv_bfloat16 h2 = __float2bfloat16(b);
    g_wn_hi[i] = h2;
    g_wn_lo[i] = __float2bfloat16(b - __bfloat162float(h2));
}

// ---------------- kernel 1: LayerNorm -> bf16 hi/lo ----------------------------
__global__ __launch_bounds__(256)
void ln_kernel(const float* __restrict__ tgt, const float* __restrict__ nbr,
               const float* __restrict__ ln_scale, const float* __restrict__ ln_bias)
{
    const int r    = blockIdx.x * 8 + (threadIdx.x >> 5);
    const int lane = threadIdx.x & 31;

    const float* src;
    __nv_bfloat16 *dh, *dl;
    if (r < BB) {
        src = tgt + (size_t)r * DD;
        dh = g_xnt_hi + (size_t)r * DD; dl = g_xnt_lo + (size_t)r * DD;
    } else {
        size_t rn = (size_t)(r - BB);
        src = nbr + rn * DD;
        dh = g_xnn_hi + rn * DD; dl = g_xnn_lo + rn * DD;
    }

    const float4* s4 = (const float4*)src;
    float4 v[8];
    float s = 0.f, q = 0.f;
    #pragma unroll
    for (int j = 0; j < 8; ++j) {
        v[j] = __ldg(s4 + j * 32 + lane);
        s += v[j].x + v[j].y + v[j].z + v[j].w;
        q += v[j].x * v[j].x + v[j].y * v[j].y + v[j].z * v[j].z + v[j].w * v[j].w;
    }
    #pragma unroll
    for (int o = 16; o > 0; o >>= 1) {
        s += __shfl_xor_sync(0xffffffffu, s, o);
        q += __shfl_xor_sync(0xffffffffu, q, o);
    }
    const float mu   = s * (1.0f / 1024.0f);
    const float var  = q * (1.0f / 1024.0f) - mu * mu;
    const float rstd = rsqrtf(var + 1e-5f);

    const float4* sc4 = (const float4*)ln_scale;
    const float4* bi4 = (const float4*)ln_bias;
    #pragma unroll
    for (int j = 0; j < 8; ++j) {
        const float4 sc = __ldg(sc4 + j * 32 + lane);
        const float4 bi = __ldg(bi4 + j * 32 + lane);
        float o0 = (v[j].x - mu) * rstd * sc.x + bi.x;
        float o1 = (v[j].y - mu) * rstd * sc.y + bi.y;
        float o2 = (v[j].z - mu) * rstd * sc.z + bi.z;
        float o3 = (v[j].w - mu) * rstd * sc.w + bi.w;
        __nv_bfloat16 h0 = __float2bfloat16(o0), h1 = __float2bfloat16(o1);
        __nv_bfloat16 h2 = __float2bfloat16(o2), h3 = __float2bfloat16(o3);
        __nv_bfloat16 l0 = __float2bfloat16(o0 - __bfloat162float(h0));
        __nv_bfloat16 l1 = __float2bfloat16(o1 - __bfloat162float(h1));
        __nv_bfloat16 l2 = __float2bfloat16(o2 - __bfloat162float(h2));
        __nv_bfloat16 l3 = __float2bfloat16(o3 - __bfloat162float(h3));
        const int d = (j * 32 + lane) * 4;
        uint2 hv, lv;
        hv.x = (uint32_t)__bfloat16_as_ushort(h0) | ((uint32_t)__bfloat16_as_ushort(h1) << 16);
        hv.y = (uint32_t)__bfloat16_as_ushort(h2) | ((uint32_t)__bfloat16_as_ushort(h3) << 16);
        lv.x = (uint32_t)__bfloat16_as_ushort(l0) | ((uint32_t)__bfloat16_as_ushort(l1) << 16);
        lv.y = (uint32_t)__bfloat16_as_ushort(l2) | ((uint32_t)__bfloat16_as_ushort(l3) << 16);
        *(uint2*)&dh[d] = hv;
        *(uint2*)&dl[d] = lv;
    }
}

// ---------------- kernel 2: merged 3xBF16 HMMA GEMM (ldmatrix, 2 CTA/SM) -------
// Row-space concat: y-tiles [0,1024) = neighbor rows, [1024,1056) = target rows.
// CTA tile 128x128, K-slab 32 bf16, double-buffered cp.async.
// 256 thr = 8 warps (4m x 2n), warp tile 32x64. Fragments via ldmatrix.x4
// (mapping bit-validated in R9). 3 terms: acc += Ah*Bh + Ah*Bl + Al*Bh.
#define ROWB 80                                 // 32 bf16 (64B) + 16B pad
#define ARR_B (128 * ROWB)                      // 10240 bytes per array
#define STAGE_B (4 * ARR_B)                     // 40960 per stage
#define GEMM_SMEM (2 * STAGE_B)                 // 81920 -> 2 CTAs/SM

__global__ __launch_bounds__(256, 2)
void gemm_all_kernel()
{
    extern __shared__ char smem[];

    const int ty = blockIdx.y;
    const __nv_bfloat16 *Ah, *Al, *Bh, *Bl;
    float* C;
    int m0;
    if (ty < (BB * KK) / 128) {
        Ah = g_xnn_hi; Al = g_xnn_lo; Bh = g_wn_hi; Bl = g_wn_lo;
        C = g_snb; m0 = ty * 128;
    } else {
        Ah = g_xnt_hi; Al = g_xnt_lo; Bh = g_ws_hi; Bl = g_ws_lo;
        C = g_sself; m0 = (ty - (BB * KK) / 128) * 128;
    }

    const int t    = threadIdx.x;
    const int e0   = blockIdx.x * 128;
    const int warp = t >> 5, lane = t & 31;
    const int g    = lane >> 2, tig = lane & 3;
    const int wm   = warp >> 1, wnb = warp & 1;
    const int mbase = wm * 32, nbase = wnb * 64;

    const uint32_t smem_s = (uint32_t)__cvta_generic_to_shared(smem);

    // ldmatrix lane offsets (R9-validated on this exact 80B-row layout):
    // A x4: lanes 0-15 -> rows m+0..15, lanes 16-31 -> same rows @k8 (+16B)
    const uint32_t a_off = (uint32_t)(mbase + (lane & 15)) * ROWB + ((lane & 16) ? 16u : 0u);
    // B x4: lanes 0-7 (n0-7,k0), 8-15 (n0-7,k8), 16-23 (n8-15,k0), 24-31 (n8-15,k8)
    const uint32_t b_off = (uint32_t)(nbase + (lane & 7) + ((lane & 16) ? 8u : 0u)) * ROWB
                         + ((lane & 8) ? 16u : 0u);

    float4 acc[2][8];
    #pragma unroll
    for (int i = 0; i < 2; ++i)
        #pragma unroll
        for (int j = 0; j < 8; ++j) acc[i][j] = make_float4(0.f, 0.f, 0.f, 0.f);

    // stage slab (32 k) into buffer: 4 arrays x 512 16B-chunks = 8 cp16/thread
    #define STAGE(slab, buf)                                                     \
        do {                                                                     \
            const int k0 = (slab) * 32;                                          \
            char* bufp = smem + (buf) * STAGE_B;                                 \
            _Pragma("unroll")                                                    \
            for (int j = 0; j < 8; ++j) {                                        \
                int i   = t + 256 * j;                                           \
                int arr = i >> 9;                                                \
                int idx = i & 511;                                               \
                int row = idx >> 2, c = idx & 3;                                 \
                const __nv_bfloat16* src =                                       \
                    (arr == 0 ? Ah : arr == 1 ? Al : arr == 2 ? Bh : Bl)         \
                    + (size_t)((arr < 2 ? m0 : e0) + row) * DD + k0 + c * 8;     \
                cp16(bufp + arr * ARR_B + row * ROWB + c * 16, src);             \
            }                                                                    \
            cp_commit();                                                         \
        } while (0)

    STAGE(0, 0);
    STAGE(1, 1);

    for (int kt = 0; kt < 32; ++kt) {
        if (kt + 1 < 32) cp_wait<1>(); else cp_wait<0>();
        __syncthreads();
        const uint32_t sbuf = smem_s + (uint32_t)(kt & 1) * STAGE_B;

        #pragma unroll
        for (int s2 = 0; s2 < 2; ++s2) {        // two k16 steps per slab
            const uint32_t kb = (uint32_t)s2 * 32;
            uint32_t ah[2][4], al[2][4];
            #pragma unroll
            for (int mt = 0; mt < 2; ++mt) {
                const uint32_t ab = a_off + (uint32_t)mt * (16 * ROWB) + kb;
                ldsm_x4(ah[mt], sbuf + ab);
                ldsm_x4(al[mt], sbuf + ARR_B + ab);
            }
            // 4 np groups of 16 e-cols; B frags ldmatrix'd per group (8+8 regs live)
            #pragma unroll
            for (int np = 0; np < 4; ++np) {
                const uint32_t bb = b_off + (uint32_t)np * (16 * ROWB) + kb;
                uint32_t bh[4], bl[4];
                ldsm_x4(bh, sbuf + 2 * ARR_B + bb);
                ldsm_x4(bl, sbuf + 3 * ARR_B + bb);
                #pragma unroll
                for (int sub = 0; sub < 2; ++sub) {
                    const int nt = np * 2 + sub;
                    uint32_t bhf[2] = { bh[sub * 2], bh[sub * 2 + 1] };
                    uint32_t blf[2] = { bl[sub * 2], bl[sub * 2 + 1] };
                    mma_bf16(acc[0][nt], ah[0], bhf);
                    mma_bf16(acc[0][nt], ah[0], blf);
                    mma_bf16(acc[0][nt], al[0], bhf);
                    mma_bf16(acc[1][nt], ah[1], bhf);
                    mma_bf16(acc[1][nt], ah[1], blf);
                    mma_bf16(acc[1][nt], al[1], bhf);
                }
            }
        }
        __syncthreads();
        if (kt + 2 < 32) STAGE(kt + 2, kt & 1);
    }
    #undef STAGE

    #pragma unroll
    for (int mt = 0; mt < 2; ++mt) {
        const int r0 = m0 + mbase + mt * 16 + g;
        #pragma unroll
        for (int nt = 0; nt < 8; ++nt) {
            const int e = e0 + nbase + nt * 8 + 2 * tig;
            const float4 v = acc[mt][nt];
            *(float2*)&C[(size_t)r0 * DD + e]       = make_float2(v.x, v.y);
            *(float2*)&C[(size_t)(r0 + 8) * DD + e] = make_float2(v.z, v.w);
        }
    }
}

// ---------------- kernel 3: epilogue -------------------------------------------
__global__ __launch_bounds__(256)
void epilogue_kernel(const float* __restrict__ dist, const float* __restrict__ beta_p,
                     const float* __restrict__ b_self, const float* __restrict__ b_nb,
                     float* __restrict__ out_selfw, float* __restrict__ out_nbw)
{
    __shared__ float dw[32];
    const int bx = blockIdx.x;
    const int b  = bx >> 2;
    const int e  = ((bx & 3) << 8) + threadIdx.x;

    if (threadIdx.x < 32) {
        float dv = __ldg(dist + (size_t)b * KK + threadIdx.x);
        dw[threadIdx.x] = expf(dv * (-2.0f / (100.0f + 1e-8f)));
    }
    __syncthreads();

    float acc[33];
    acc[0] = g_sself[(size_t)b * DD + e] + __ldg(b_self + e);
    const float bn = __ldg(b_nb + e);
    #pragma unroll
    for (int k = 0; k < KK; ++k)
        acc[k + 1] = (g_snb[((size_t)b * KK + k) * DD + e] + bn) * dw[k];

    float mx = acc[0];
    #pragma unroll
    for (int m = 1; m < 33; ++m) mx = fmaxf(mx, acc[m]);
    float sum = 0.f;
    #pragma unroll
    for (int m = 0; m < 33; ++m) { acc[m] = fast_exp(acc[m] - mx); sum += acc[m]; }
    const float inv = 1.0f / sum;
    #pragma unroll
    for (int m = 0; m < 33; ++m) {
        const float w = acc[m] * inv;
        acc[m] = (fabsf(w) >= 0.01f) ? w : 0.0f;
    }

    const float beta = __ldg(beta_p);
    out_selfw[(size_t)b * DD + e] = acc[0];
    const size_t ti = (size_t)b * DD + e;
    const float xnt = __bfloat162float(g_xnt_hi[ti]) + __bfloat162float(g_xnt_lo[ti]);
    float ctx = beta * acc[0] * xnt;
    float ns  = 0.f;
    #pragma unroll
    for (int k = 0; k < KK; ++k) {
        const float w = acc[k + 1];
        const size_t ni = ((size_t)b * KK + k) * DD + e;
        out_nbw[ni] = w;
        const float xnn = __bfloat162float(g_xnn_hi[ni]) + __bfloat162float(g_xnn_lo[ni]);
        ns += w * xnn;
    }
    ctx += (1.0f - beta) * ns;
    g_ctx[(size_t)b * DD + e] = ctx;
}

// ---------------- kernel 4: reduced = leaky_relu(ctx @ w_red^T + b_red) --------
__global__ __launch_bounds__(256)
void reduce_kernel(const float* __restrict__ w_red, const float* __restrict__ b_red,
                   float* __restrict__ out_red)
{
    __shared__ float ctx_s[32 * 33];
    __shared__ float w_s[128 * 33];

    const int t  = threadIdx.x;
    const int b0 = blockIdx.x * 32;
    const int tb = t >> 4;
    const int tr = t & 15;

    float acc[2][8];
    #pragma unroll
    for (int i = 0; i < 8; ++i) { acc[0][i] = 0.f; acc[1][i] = 0.f; }

    for (int d0 = 0; d0 < DD; d0 += 32) {
        __syncthreads();
        #pragma unroll
        for (int j = 0; j < 4; ++j) {
            int i = t + 256 * j;
            int row = i >> 5, col = i & 31;
            ctx_s[row * 33 + col] = g_ctx[(size_t)(b0 + row) * DD + d0 + col];
        }
        #pragma unroll
        for (int j = 0; j < 16; ++j) {
            int i = t + 256 * j;
            int row = i >> 5, col = i & 31;
            w_s[row * 33 + col] = __ldg(w_red + (size_t)row * DD + d0 + col);
        }
        __syncthreads();

        #pragma unroll
        for (int dl = 0; dl < 32; ++dl) {
            float c0 = ctx_s[tb * 33 + dl];
            float c1 = ctx_s[(tb + 16) * 33 + dl];
            #pragma unroll
            for (int i = 0; i < 8; ++i) {
                float wv = w_s[(tr + 16 * i) * 33 + dl];
                acc[0][i] += c0 * wv;
                acc[1][i] += c1 * wv;
            }
        }
    }

    #pragma unroll
    for (int i = 0; i < 8; ++i) {
        int r = tr + 16 * i;
        float bias = __ldg(b_red + r);
        float v0 = acc[0][i] + bias;
        float v1 = acc[1][i] + bias;
        v0 = v0 > 0.f ? v0 : 0.01f * v0;
        v1 = v1 > 0.f ? v1 : 0.01f * v1;
        out_red[(size_t)(b0 + tb) * RR + r]      = v0;
        out_red[(size_t)(b0 + tb + 16) * RR + r] = v1;
    }
}

// ---------------------------------------------------------------------------
extern "C" void kernel_launch(void* const* d_in, const int* in_sizes, int n_in,
                              void* d_out, int out_size)
{
    (void)in_sizes; (void)n_in; (void)out_size;

    const float* tgt      = (const float*)d_in[0];
    const float* nbr      = (const float*)d_in[1];
    const float* dist     = (const float*)d_in[2];
    const float* beta_p   = (const float*)d_in[3];
    const float* ln_scale = (const float*)d_in[4];
    const float* ln_bias  = (const float*)d_in[5];
    const float* w_self   = (const float*)d_in[6];
    const float* b_self   = (const float*)d_in[7];
    const float* w_nb     = (const float*)d_in[8];
    const float* b_nb     = (const float*)d_in[9];
    const float* w_red    = (const float*)d_in[10];
    const float* b_red    = (const float*)d_in[11];

    float* out       = (float*)d_out;
    float* out_red   = out;                              // B*R
    float* out_selfw = out + (size_t)BB * RR;            // B*D
    float* out_nbw   = out_selfw + (size_t)BB * DD;      // B*K*D

    cudaFuncSetAttribute(gemm_all_kernel,
                         cudaFuncAttributeMaxDynamicSharedMemorySize, GEMM_SMEM);

    wprep_kernel<<<DD * DD / 256, 256>>>(w_self, w_nb);
    ln_kernel<<<(BB * 33) / 8, 256>>>(tgt, nbr, ln_scale, ln_bias);

    // merged: y in [0,1024) -> neighbor GEMM, [1024,1056) -> self GEMM
    gemm_all_kernel<<<dim3(DD / 128, (BB * KK) / 128 + BB / 128), 256, GEMM_SMEM>>>();

    epilogue_kernel<<<BB * 4, 256>>>(dist, beta_p, b_self, b_nb, out_selfw, out_nbw);
    reduce_kernel<<<BB / 32, 256>>>(w_red, b_red, out_red);
}